// round 12
// baseline (speedup 1.0000x reference)
#include <cuda_runtime.h>
#include <cstdint>

#define NB 16
#define NC 64
#define NT 2048
#define KNN 3
#define NTILE 16      // NT/128
#define NPAIR 136     // NTILE*(NTILE+1)/2

// scratch (static __device__ arrays: allocation-free per harness rules)
__device__ float g_cs[(size_t)NB * NT * NTILE * KNN];  // candidate scores
__device__ int   g_ci[(size_t)NB * NT * NTILE * KNN];  // candidate indices

// ---------------- f32x2 helpers (sm_100+ packed fp32 FMA) --------------------------
__device__ __forceinline__ unsigned long long dup2(float v) {
    unsigned long long r;
    asm("mov.b64 %0, {%1, %1};" : "=l"(r) : "f"(v));
    return r;
}
__device__ __forceinline__ void fma2(unsigned long long& d, unsigned long long a, unsigned long long b) {
    asm("fma.rn.f32x2 %0, %1, %2, %0;" : "+l"(d) : "l"(a), "l"(b));
}
__device__ __forceinline__ void unpack2(unsigned long long v, float& lo, float& hi) {
    asm("mov.b64 {%0, %1}, %2;" : "=f"(lo), "=f"(hi) : "l"(v));
}
__device__ __forceinline__ uint32_t smem_u32(const void* p) {
    uint32_t a;
    asm("{ .reg .u64 t; cvta.to.shared.u64 t, %1; cvt.u32.u64 %0, t; }" : "=r"(a) : "l"(p));
    return a;
}
__device__ __forceinline__ void cp_async16(uint32_t dst, const void* src) {
    asm volatile("cp.async.ca.shared.global [%0], [%1], 16;" :: "r"(dst), "l"(src) : "memory");
}
__device__ __forceinline__ void cp_async4(uint32_t dst, const void* src) {
    asm volatile("cp.async.ca.shared.global [%0], [%1], 4;" :: "r"(dst), "l"(src) : "memory");
}
#define CP_COMMIT()   asm volatile("cp.async.commit_group;" ::: "memory")
#define CP_WAIT(n)    asm volatile("cp.async.wait_group %0;" :: "n"(n) : "memory")

// top-3 insert with (score, index) lexicographic tie-break (== lax.top_k stability)
#define INS3(SC, SI)                                                          \
    do {                                                                      \
        float _s = (SC); int _i = (SI);                                       \
        if (_s < q2 || (_s == q2 && _i < j2)) {                               \
            q2 = _s; j2 = _i;                                                 \
            if (q2 < q1 || (q2 == q1 && j2 < j1)) {                           \
                float _t = q1; q1 = q2; q2 = _t;                              \
                int _k = j1; j1 = j2; j2 = _k;                                \
                if (q1 < q0 || (q1 == q0 && j1 < j0)) {                       \
                    _t = q0; q0 = q1; q1 = _t;                                \
                    _k = j0; j0 = j1; j1 = _k;                                \
                }                                                             \
            }                                                                 \
        }                                                                     \
    } while (0)

// ---------------- kernel 1: gram + nsq + bidirectional top-3 (unchanged R11) -------
extern __shared__ float smem[];

__global__ __launch_bounds__(256) void gram_kernel(const float* __restrict__ x) {
    float* At   = smem;                 // [64][128]   (phase 1)
    float* Bs   = smem + 64 * 128;      // [64][128]   (phase 1)
    float* score = smem;                // [128][132]  (phase 2 overlay)
    float* nsqR = smem + 128 * 132;     // [128]
    float* nsqC = nsqR + 128;           // [128]

    const int tid = threadIdx.x;
    const int tx  = tid & 7;    // col-pair group: pairs tx + 8q
    const int ty  = tid >> 3;   // row group: rows ty*4 .. +3
    const int b   = blockIdx.y;

    // closed-form upper-triangle decode: p -> (ti, tj), tj >= ti
    const int p = blockIdx.x;
    int ti = (int)(NTILE + 0.5f - sqrtf((NTILE + 0.5f) * (NTILE + 0.5f) - 2.0f * p));
    int off = ti * NTILE - (ti * (ti - 1)) / 2;
    if (p < off)                    { ti--; off = ti * NTILE - (ti * (ti - 1)) / 2; }
    else if (p >= off + NTILE - ti) { ti++; off = ti * NTILE - (ti * (ti - 1)) / 2; }
    const int tj = ti + (p - off);
    const int t0 = ti * 128, s0 = tj * 128;
    const bool diag = (ti == tj);

    const float4* xb4 = (const float4*)(x + (size_t)b * NC * NT);
    const uint32_t atb = smem_u32(At);
    const uint32_t bsb = smem_u32(Bs);

    // ---- stage tiles via cp.async (8 x 16B per thread per tile) ----
#pragma unroll
    for (int it = 0; it < 8; it++) {
        int i = tid + it * 256;
        int c = i >> 5, t4 = i & 31;
        cp_async16(atb + (c * 128 + 4 * t4) * 4, &xb4[c * (NT / 4) + (t0 >> 2) + t4]);
    }
#pragma unroll
    for (int it = 0; it < 8; it++) {
        int i = tid + it * 256;
        int c = i >> 5, t4 = i & 31;
        cp_async16(bsb + (c * 128 + 4 * t4) * 4, &xb4[c * (NT / 4) + (s0 >> 2) + t4]);
    }
    CP_COMMIT();
    CP_WAIT(0);
    __syncthreads();

    // ---- in-kernel nsq (bit-identical two-half sums) ----
    {
        const float* src = (tid < 128) ? At : Bs;
        float* dst       = (tid < 128) ? nsqR : nsqC;
        int t = tid & 127;
        float s0h = 0.f, s1h = 0.f;
#pragma unroll
        for (int c = 0; c < 32; c++) {
            float v = src[c * 128 + t];
            s0h = fmaf(v, v, s0h);
        }
#pragma unroll
        for (int c = 32; c < 64; c++) {
            float v = src[c * 128 + t];
            s1h = fmaf(v, v, s1h);
        }
        dst[t] = s0h + s1h;
    }

    // ---- mainloop (R4-exact) ----
    unsigned long long acc[4][8];
#pragma unroll
    for (int r = 0; r < 4; r++)
#pragma unroll
        for (int q = 0; q < 8; q++) acc[r][q] = 0ull;

#pragma unroll 8
    for (int c = 0; c < 64; c++) {
        float4 a4 = *(const float4*)&At[c * 128 + ty * 4];
        unsigned long long ad0 = dup2(a4.x), ad1 = dup2(a4.y);
        unsigned long long ad2 = dup2(a4.z), ad3 = dup2(a4.w);
        const unsigned long long* bq = (const unsigned long long*)&Bs[c * 128];
        unsigned long long bv[8];
#pragma unroll
        for (int q = 0; q < 8; q++) bv[q] = bq[tx + 8 * q];   // 4-way broadcast
#pragma unroll
        for (int q = 0; q < 8; q++) {
            fma2(acc[0][q], ad0, bv[q]);
            fma2(acc[1][q], ad1, bv[q]);
            fma2(acc[2][q], ad2, bv[q]);
            fma2(acc[3][q], ad3, bv[q]);
        }
    }
    __syncthreads();   // At/Bs reads + nsq writes done before score overlays tiles

    // ---- dump dot tile: STS.64, conflict-free (132 = 4 mod 16 padding) ----
#pragma unroll
    for (int r = 0; r < 4; r++)
#pragma unroll
        for (int q = 0; q < 8; q++)
            *(unsigned long long*)&score[(ty * 4 + r) * 132 + 2 * (tx + 8 * q)] = acc[r][q];
    __syncthreads();

    if (tid < 128) {
        // row scan (float2: 64 skewed pair-iterations)
        float q0 = 3.4e38f, q1 = 3.4e38f, q2 = 3.4e38f;
        int   j0 = 0x7fffffff, j1 = 0x7fffffff, j2 = 0x7fffffff;
        const float2* rowp2 = (const float2*)&score[tid * 132];
        const float2* nsc2  = (const float2*)nsqC;
#pragma unroll 4
        for (int i = 0; i < 64; i++) {
            int pj = (i + tid) & 63;
            float2 d2 = rowp2[pj];
            float2 n2 = nsc2[pj];
            float scl = fmaf(-2.f, d2.x, n2.x);
            float sch = fmaf(-2.f, d2.y, n2.y);
            INS3(scl, s0 + 2 * pj);
            INS3(sch, s0 + 2 * pj + 1);
        }
        size_t base = ((size_t)(b * NT + t0 + tid) * NTILE + tj) * KNN;
        g_cs[base + 0] = q0; g_ci[base + 0] = j0;
        g_cs[base + 1] = q1; g_ci[base + 1] = j1;
        g_cs[base + 2] = q2; g_ci[base + 2] = j2;
    } else if (!diag) {
        // column scan
        int cc = tid - 128;
        float q0 = 3.4e38f, q1 = 3.4e38f, q2 = 3.4e38f;
        int   j0 = 0x7fffffff, j1 = 0x7fffffff, j2 = 0x7fffffff;
#pragma unroll 4
        for (int i = 0; i < 128; i++) {
            int jj = (i + cc) & 127;
            float sc = fmaf(-2.f, score[jj * 132 + cc], nsqR[jj]);
            INS3(sc, t0 + jj);
        }
        size_t base = ((size_t)(b * NT + s0 + cc) * NTILE + ti) * KNN;
        g_cs[base + 0] = q0; g_ci[base + 0] = j0;
        g_cs[base + 1] = q1; g_ci[base + 1] = j1;
        g_cs[base + 2] = q2; g_ci[base + 2] = j2;
    }
}

// ---------------- kernel 2: merge + pipelined gather + conv ------------------------
// out[b,o,t] = bias[o] + sum_j W[o*192+j] * x[b, j/3, idx[b,t,j%3]]
// W processed in three 64-j chunks; W and ps chunks double-buffered via cp.async:
// W0/W1 copies overlap the candidate merge; ps0/ps1 issued after sidx; chunk 2
// issued during phase-0 compute. Accumulation order over j unchanged (bit-exact).
// smem floats: wc[2][4096] | ps[2][8192] | sidx[384]  = 24960 floats (99840 B)
#define CV_WC 0
#define CV_PS 8192
#define CV_SIDX 24576
#define CONV_SMEM_BYTES (24960 * 4)

__device__ __forceinline__ void conv_issue_w(uint32_t wcb, const float* __restrict__ W,
                                             int buf, int jc, int tid) {
#pragma unroll
    for (int it = 0; it < 16; it++) {
        int i = tid + it * 256;                      // i = jj*64 + o
        int jj = i >> 6, o = i & 63;
        cp_async4(wcb + (buf * 4096 + i) * 4, &W[o * 192 + jc * 64 + jj]);
    }
}
__device__ __forceinline__ void conv_issue_ps(uint32_t psb, const float* __restrict__ xb,
                                              const int* sidx, int buf, int jc, int tid) {
#pragma unroll 4
    for (int it = 0; it < 32; it++) {
        int i = tid + it * 256;                      // i = jj*128 + tl
        int jj = i >> 7, tl = i & 127;
        int j  = jc * 64 + jj;
        int ch = j / 3;
        int kk = j - ch * 3;
        cp_async4(psb + (buf * 8192 + i) * 4, &xb[(size_t)ch * NT + sidx[tl * KNN + kk]]);
    }
}
__device__ __forceinline__ void conv_compute(const float* wc, const float* ps,
                                             unsigned long long acc2[4][4], int to, int tt) {
#pragma unroll 8
    for (int jj = 0; jj < 64; jj++) {
        float4 w4 = *(const float4*)&wc[jj * 64 + to * 4];
        unsigned long long wd0 = dup2(w4.x), wd1 = dup2(w4.y);
        unsigned long long wd2 = dup2(w4.z), wd3 = dup2(w4.w);
        const unsigned long long* pr = (const unsigned long long*)&ps[jj * 128 + tt * 8];
#pragma unroll
        for (int e = 0; e < 4; e++) {
            unsigned long long pv = pr[e];
            fma2(acc2[0][e], wd0, pv);
            fma2(acc2[1][e], wd1, pv);
            fma2(acc2[2][e], wd2, pv);
            fma2(acc2[3][e], wd3, pv);
        }
    }
}

__global__ __launch_bounds__(256) void conv_kernel(const float* __restrict__ x,
                                                   const float* __restrict__ W,
                                                   const float* __restrict__ bias,
                                                   float* __restrict__ out) {
    const int b  = blockIdx.y;
    const int t0 = blockIdx.x * 128;
    const int tid = threadIdx.x;

    float* wc   = smem + CV_WC;                     // [2][64 j][64 o]
    float* ps   = smem + CV_PS;                     // [2][64 j][128 t]
    int*   sidx = (int*)(smem + CV_SIDX);           // [128*3]
    const uint32_t wcb = smem_u32(wc);
    const uint32_t psb = smem_u32(ps);
    const float* xb = x + (size_t)b * NC * NT;

    // prefetch W chunks 0 and 1 (groups g0, g1) — overlaps the merge below
    conv_issue_w(wcb, W, 0, 0, tid); CP_COMMIT();
    conv_issue_w(wcb, W, 1, 1, tid); CP_COMMIT();

    // merge this block's 128 rows: 16 slots x 3 candidates -> final top-3
    if (tid < 128) {
        size_t cb = (size_t)(b * NT + t0 + tid) * (NTILE * KNN);
        float q0 = 3.4e38f, q1 = 3.4e38f, q2 = 3.4e38f;
        int   j0 = 0x7fffffff, j1 = 0x7fffffff, j2 = 0x7fffffff;
#pragma unroll 8
        for (int e = 0; e < NTILE * KNN; e++) {
            float sc = g_cs[cb + e];
            int   si = g_ci[cb + e];
            INS3(sc, si);
        }
        sidx[tid * KNN + 0] = j0;
        sidx[tid * KNN + 1] = j1;
        sidx[tid * KNN + 2] = j2;
    }
    __syncthreads();   // sidx visible to all

    // ps gathers for phases 0 and 1 (groups g2, g3)
    conv_issue_ps(psb, xb, sidx, 0, 0, tid); CP_COMMIT();
    conv_issue_ps(psb, xb, sidx, 1, 1, tid); CP_COMMIT();

    const int to = tid & 15;   // o-group: o = to*4 .. +3
    const int tt = tid >> 4;   // t-group: t = tt*8 .. +7 (4 pairs)
    unsigned long long acc2[4][4];
#pragma unroll
    for (int r = 0; r < 4; r++)
#pragma unroll
        for (int e = 0; e < 4; e++) acc2[r][e] = 0ull;

    // phase 0: wait W0+ps0 (g3 may remain pending)
    CP_WAIT(1);
    __syncthreads();
    conv_compute(wc, ps, acc2, to, tt);
    __syncthreads();   // buffers 0 free

    // issue chunk 2 into buffer 0 (group g4) — overlaps phase-1 compute
    conv_issue_w(wcb, W, 0, 2, tid);
    conv_issue_ps(psb, xb, sidx, 0, 2, tid);
    CP_COMMIT();

    // phase 1: wait g3 (g4 may remain pending)
    CP_WAIT(1);
    __syncthreads();
    conv_compute(wc + 4096, ps + 8192, acc2, to, tt);
    __syncthreads();   // (keeps buffer-1 lifetime clean; g4 targets buffer 0)

    // phase 2
    CP_WAIT(0);
    __syncthreads();
    conv_compute(wc, ps, acc2, to, tt);

#pragma unroll
    for (int r = 0; r < 4; r++) {
        int o = to * 4 + r;
        float bo = __ldg(&bias[o]);
        float* op = out + ((size_t)(b * NC + o)) * NT + t0 + tt * 8;
#pragma unroll
        for (int e = 0; e < 4; e++) {
            float lo, hi;
            unpack2(acc2[r][e], lo, hi);
            *(float2*)&op[2 * e] = make_float2(lo + bo, hi + bo);
        }
    }
}

// ---------------- launch -----------------------------------------------------------
extern "C" void kernel_launch(void* const* d_in, const int* in_sizes, int n_in,
                              void* d_out, int out_size) {
    const float* x    = (const float*)d_in[0];
    const float* W    = (const float*)d_in[1];
    const float* bias = (const float*)d_in[2];
    float* out        = (float*)d_out;

    const int gram_smem = (128 * 132 + 256) * 4;                          // 68608 B
    cudaFuncSetAttribute(gram_kernel, cudaFuncAttributeMaxDynamicSharedMemorySize, gram_smem);
    cudaFuncSetAttribute(conv_kernel, cudaFuncAttributeMaxDynamicSharedMemorySize, CONV_SMEM_BYTES);

    gram_kernel<<<dim3(NPAIR, NB), 256, gram_smem>>>(x);
    conv_kernel<<<dim3(NT / 128, NB), 256, CONV_SMEM_BYTES>>>(x, W, bias, out);
}

// round 14
// speedup vs baseline: 1.1136x; 1.1136x over previous
#include <cuda_runtime.h>
#include <cstdint>

#define NB 16
#define NC 64
#define NT 2048
#define KNN 3
#define NTILE 16      // NT/128
#define NPAIR 136     // NTILE*(NTILE+1)/2

// scratch (static __device__ arrays: allocation-free per harness rules)
__device__ float g_cs[(size_t)NB * NT * NTILE * KNN];  // candidate scores
__device__ int   g_ci[(size_t)NB * NT * NTILE * KNN];  // candidate indices
__device__ float g_xT[(size_t)NB * NT * NC];           // x transposed: [b][t][c]
__device__ float g_W2[3 * 32 * 64 * 2];                // W re-packed: [(kk,chp)][o] float2(ch pair)

// ---------------- f32x2 helpers (sm_100+ packed fp32 FMA) --------------------------
__device__ __forceinline__ unsigned long long dup2(float v) {
    unsigned long long r;
    asm("mov.b64 %0, {%1, %1};" : "=l"(r) : "f"(v));
    return r;
}
__device__ __forceinline__ void fma2(unsigned long long& d, unsigned long long a, unsigned long long b) {
    asm("fma.rn.f32x2 %0, %1, %2, %0;" : "+l"(d) : "l"(a), "l"(b));
}
__device__ __forceinline__ void unpack2(unsigned long long v, float& lo, float& hi) {
    asm("mov.b64 {%0, %1}, %2;" : "=f"(lo), "=f"(hi) : "l"(v));
}
__device__ __forceinline__ uint32_t smem_u32(const void* p) {
    uint32_t a;
    asm("{ .reg .u64 t; cvta.to.shared.u64 t, %1; cvt.u32.u64 %0, t; }" : "=r"(a) : "l"(p));
    return a;
}
__device__ __forceinline__ void cp_async16(uint32_t dst, const void* src) {
    asm volatile("cp.async.ca.shared.global [%0], [%1], 16;" :: "r"(dst), "l"(src) : "memory");
}
__device__ __forceinline__ void cp_async8(uint32_t dst, const void* src) {
    asm volatile("cp.async.ca.shared.global [%0], [%1], 8;" :: "r"(dst), "l"(src) : "memory");
}
#define CP_COMMIT()   asm volatile("cp.async.commit_group;" ::: "memory")
#define CP_WAIT(n)    asm volatile("cp.async.wait_group %0;" :: "n"(n) : "memory")

// top-3 insert with (score, index) lexicographic tie-break (== lax.top_k stability)
#define INS3(SC, SI)                                                          \
    do {                                                                      \
        float _s = (SC); int _i = (SI);                                       \
        if (_s < q2 || (_s == q2 && _i < j2)) {                               \
            q2 = _s; j2 = _i;                                                 \
            if (q2 < q1 || (q2 == q1 && j2 < j1)) {                           \
                float _t = q1; q1 = q2; q2 = _t;                              \
                int _k = j1; j1 = j2; j2 = _k;                                \
                if (q1 < q0 || (q1 == q0 && j1 < j0)) {                       \
                    _t = q0; q0 = q1; q1 = _t;                                \
                    _k = j0; j0 = j1; j1 = _k;                                \
                }                                                             \
            }                                                                 \
        }                                                                     \
    } while (0)

extern __shared__ float smem[];

// ---------------- kernel 0a: transpose x -> xT[b][t][c] ----------------------------
__global__ __launch_bounds__(256) void transpose_kernel(const float* __restrict__ x) {
    __shared__ float S[64 * 33];
    const int b  = blockIdx.y;
    const int t0 = blockIdx.x * 32;
    const int tid = threadIdx.x;
    const float* xb = x + (size_t)b * NC * NT;
#pragma unroll
    for (int it = 0; it < 8; it++) {
        int i = tid + it * 256;
        int c = i >> 5, tl = i & 31;
        S[c * 33 + tl] = xb[(size_t)c * NT + t0 + tl];   // coalesced read
    }
    __syncthreads();
#pragma unroll
    for (int it = 0; it < 8; it++) {
        int i = tid + it * 256;
        int t = i >> 6, cc = i & 63;
        g_xT[((size_t)b * NT + t0 + t) * NC + cc] = S[cc * 33 + t];  // coalesced write
    }
}

// ---------------- kernel 0b: repack W -> g_W2[(kk,chp)][o] = (W[o][2chp*3+kk], W[o][(2chp+1)*3+kk])
__global__ __launch_bounds__(256) void prep_w_kernel(const float* __restrict__ W) {
    int gid = blockIdx.x * 256 + threadIdx.x;     // 6144 entries
    int o = gid & 63;
    int rest = gid >> 6;
    int chp = rest & 31;
    int kk  = rest >> 5;                          // 0..2
    g_W2[gid * 2 + 0] = W[o * 192 + (2 * chp)     * 3 + kk];
    g_W2[gid * 2 + 1] = W[o * 192 + (2 * chp + 1) * 3 + kk];
}

// ---------------- kernel 1: gram + nsq + bidirectional top-3 (unchanged R11) -------
__global__ __launch_bounds__(256) void gram_kernel(const float* __restrict__ x) {
    float* At   = smem;                 // [64][128]   (phase 1)
    float* Bs   = smem + 64 * 128;      // [64][128]   (phase 1)
    float* score = smem;                // [128][132]  (phase 2 overlay)
    float* nsqR = smem + 128 * 132;     // [128]
    float* nsqC = nsqR + 128;           // [128]

    const int tid = threadIdx.x;
    const int tx  = tid & 7;
    const int ty  = tid >> 3;
    const int b   = blockIdx.y;

    const int p = blockIdx.x;
    int ti = (int)(NTILE + 0.5f - sqrtf((NTILE + 0.5f) * (NTILE + 0.5f) - 2.0f * p));
    int off = ti * NTILE - (ti * (ti - 1)) / 2;
    if (p < off)                    { ti--; off = ti * NTILE - (ti * (ti - 1)) / 2; }
    else if (p >= off + NTILE - ti) { ti++; off = ti * NTILE - (ti * (ti - 1)) / 2; }
    const int tj = ti + (p - off);
    const int t0 = ti * 128, s0 = tj * 128;
    const bool diag = (ti == tj);

    const float4* xb4 = (const float4*)(x + (size_t)b * NC * NT);
    const uint32_t atb = smem_u32(At);
    const uint32_t bsb = smem_u32(Bs);

#pragma unroll
    for (int it = 0; it < 8; it++) {
        int i = tid + it * 256;
        int c = i >> 5, t4 = i & 31;
        cp_async16(atb + (c * 128 + 4 * t4) * 4, &xb4[c * (NT / 4) + (t0 >> 2) + t4]);
    }
#pragma unroll
    for (int it = 0; it < 8; it++) {
        int i = tid + it * 256;
        int c = i >> 5, t4 = i & 31;
        cp_async16(bsb + (c * 128 + 4 * t4) * 4, &xb4[c * (NT / 4) + (s0 >> 2) + t4]);
    }
    CP_COMMIT();
    CP_WAIT(0);
    __syncthreads();

    {   // in-kernel nsq (bit-identical two-half sums)
        const float* src = (tid < 128) ? At : Bs;
        float* dst       = (tid < 128) ? nsqR : nsqC;
        int t = tid & 127;
        float s0h = 0.f, s1h = 0.f;
#pragma unroll
        for (int c = 0; c < 32; c++) { float v = src[c * 128 + t]; s0h = fmaf(v, v, s0h); }
#pragma unroll
        for (int c = 32; c < 64; c++) { float v = src[c * 128 + t]; s1h = fmaf(v, v, s1h); }
        dst[t] = s0h + s1h;
    }

    unsigned long long acc[4][8];
#pragma unroll
    for (int r = 0; r < 4; r++)
#pragma unroll
        for (int q = 0; q < 8; q++) acc[r][q] = 0ull;

#pragma unroll 8
    for (int c = 0; c < 64; c++) {
        float4 a4 = *(const float4*)&At[c * 128 + ty * 4];
        unsigned long long ad0 = dup2(a4.x), ad1 = dup2(a4.y);
        unsigned long long ad2 = dup2(a4.z), ad3 = dup2(a4.w);
        const unsigned long long* bq = (const unsigned long long*)&Bs[c * 128];
        unsigned long long bv[8];
#pragma unroll
        for (int q = 0; q < 8; q++) bv[q] = bq[tx + 8 * q];
#pragma unroll
        for (int q = 0; q < 8; q++) {
            fma2(acc[0][q], ad0, bv[q]);
            fma2(acc[1][q], ad1, bv[q]);
            fma2(acc[2][q], ad2, bv[q]);
            fma2(acc[3][q], ad3, bv[q]);
        }
    }
    __syncthreads();

#pragma unroll
    for (int r = 0; r < 4; r++)
#pragma unroll
        for (int q = 0; q < 8; q++)
            *(unsigned long long*)&score[(ty * 4 + r) * 132 + 2 * (tx + 8 * q)] = acc[r][q];
    __syncthreads();

    const float* nsqRr = smem + 128 * 132;
    const float* nsqCr = nsqRr + 128;
    if (tid < 128) {
        float q0 = 3.4e38f, q1 = 3.4e38f, q2 = 3.4e38f;
        int   j0 = 0x7fffffff, j1 = 0x7fffffff, j2 = 0x7fffffff;
        const float2* rowp2 = (const float2*)&score[tid * 132];
        const float2* nsc2  = (const float2*)nsqCr;
#pragma unroll 4
        for (int i = 0; i < 64; i++) {
            int pj = (i + tid) & 63;
            float2 d2 = rowp2[pj];
            float2 n2 = nsc2[pj];
            float scl = fmaf(-2.f, d2.x, n2.x);
            float sch = fmaf(-2.f, d2.y, n2.y);
            INS3(scl, s0 + 2 * pj);
            INS3(sch, s0 + 2 * pj + 1);
        }
        size_t base = ((size_t)(b * NT + t0 + tid) * NTILE + tj) * KNN;
        g_cs[base + 0] = q0; g_ci[base + 0] = j0;
        g_cs[base + 1] = q1; g_ci[base + 1] = j1;
        g_cs[base + 2] = q2; g_ci[base + 2] = j2;
    } else if (!diag) {
        int cc = tid - 128;
        float q0 = 3.4e38f, q1 = 3.4e38f, q2 = 3.4e38f;
        int   j0 = 0x7fffffff, j1 = 0x7fffffff, j2 = 0x7fffffff;
#pragma unroll 4
        for (int i = 0; i < 128; i++) {
            int jj = (i + cc) & 127;
            float sc = fmaf(-2.f, score[jj * 132 + cc], nsqRr[jj]);
            INS3(sc, t0 + jj);
        }
        size_t base = ((size_t)(b * NT + s0 + cc) * NTILE + ti) * KNN;
        g_cs[base + 0] = q0; g_ci[base + 0] = j0;
        g_cs[base + 1] = q1; g_ci[base + 1] = j1;
        g_cs[base + 2] = q2; g_ci[base + 2] = j2;
    }
}

// ---------------- kernel 2: merge + coalesced row-gather + conv --------------------
// 64 tokens per block. G[(tl,kk)][ch] gathered as whole 256B xT rows (cp.async 8B);
// out[o][t] = bias + sum_{kk,chp} W2[(kk,chp)][o] . G[(tl,kk)][2chp..2chp+1]  (f32x2)
#define CV_W2   0                       // 12288 floats: [(kk*32+chp)][o] float2
#define CV_G    12288                   // 12288 floats: [192 rows][64 ch]
#define CV_SIDX 24576                   // 192 ints
#define CONV_SMEM_BYTES ((24576 + 192) * 4)   // 99072 B -> 2 blocks/SM

__global__ __launch_bounds__(256) void conv_kernel(const float* __restrict__ bias,
                                                   float* __restrict__ out) {
    const int b   = blockIdx.y;
    const int t0  = blockIdx.x * 64;
    const int tid = threadIdx.x;
    const int wid = tid >> 5, lane = tid & 31;

    float* Ws2  = smem + CV_W2;
    float* G    = smem + CV_G;
    int*   sidx = (int*)(smem + CV_SIDX);
    const uint32_t wsb = smem_u32(Ws2);
    const uint32_t gb  = smem_u32(G);

    // stage W2 (48KB contiguous, L2-resident) — overlaps the merge
#pragma unroll
    for (int it = 0; it < 12; it++) {
        int i = tid + it * 256;                       // float4 index, 3072 total
        cp_async16(wsb + i * 16, &g_W2[i * 4]);
    }
    CP_COMMIT();

    // merge: 64 tokens, 16 slots x 3 candidates each -> final top-3
    if (tid < 64) {
        size_t cb = (size_t)(b * NT + t0 + tid) * (NTILE * KNN);
        float q0 = 3.4e38f, q1 = 3.4e38f, q2 = 3.4e38f;
        int   j0 = 0x7fffffff, j1 = 0x7fffffff, j2 = 0x7fffffff;
#pragma unroll 8
        for (int e = 0; e < NTILE * KNN; e++) {
            float sc = g_cs[cb + e];
            int   si = g_ci[cb + e];
            INS3(sc, si);
        }
        sidx[tid * KNN + 0] = j0;
        sidx[tid * KNN + 1] = j1;
        sidx[tid * KNN + 2] = j2;
    }
    __syncthreads();

    // gather: 192 rows x 256B, one warp-load per row (coalesced!)
    const float* xTb = &g_xT[(size_t)b * NT * NC];
    for (int ri = wid; ri < 192; ri += 8) {
        int nv = sidx[ri];
        cp_async8(gb + (ri * 64 + 2 * lane) * 4, &xTb[(size_t)nv * NC + 2 * lane]);
    }
    CP_COMMIT();
    CP_WAIT(0);
    __syncthreads();

    // compute: thread (to: 4 o's, tt: 4 t's), f32x2 packed over channel pairs
    const int to = tid & 15;   // o = to*4 .. +3
    const int tt = tid >> 4;   // t = t0 + tt*4 .. +3
    unsigned long long acc2[4][4];
#pragma unroll
    for (int r = 0; r < 4; r++)
#pragma unroll
        for (int e = 0; e < 4; e++) acc2[r][e] = 0ull;

#pragma unroll
    for (int kk = 0; kk < 3; kk++) {
#pragma unroll 8
        for (int chp = 0; chp < 32; chp++) {
            int jp = kk * 32 + chp;
            // W2 for o = to*4..+3 : LDS.64 quads (4-way conflicted but fma-pipe still binds)
            const unsigned long long* wp = (const unsigned long long*)&Ws2[(jp * 64 + to * 4) * 2];
            unsigned long long w0 = wp[0], w1 = wp[1], w2 = wp[2], w3 = wp[3];
#pragma unroll
            for (int e = 0; e < 4; e++) {
                int ri = (tt * 4 + e) * 3 + kk;
                unsigned long long gv = *(const unsigned long long*)&G[ri * 64 + 2 * chp];
                fma2(acc2[0][e], w0, gv);
                fma2(acc2[1][e], w1, gv);
                fma2(acc2[2][e], w2, gv);
                fma2(acc2[3][e], w3, gv);
            }
        }
    }

#pragma unroll
    for (int r = 0; r < 4; r++) {
        int o = to * 4 + r;
        float bo = __ldg(&bias[o]);
        float4 res;
        float lo, hi;
        unpack2(acc2[r][0], lo, hi); res.x = lo + hi + bo;
        unpack2(acc2[r][1], lo, hi); res.y = lo + hi + bo;
        unpack2(acc2[r][2], lo, hi); res.z = lo + hi + bo;
        unpack2(acc2[r][3], lo, hi); res.w = lo + hi + bo;
        *(float4*)&out[((size_t)(b * NC + o)) * NT + t0 + tt * 4] = res;
    }
}

// ---------------- launch -----------------------------------------------------------
extern "C" void kernel_launch(void* const* d_in, const int* in_sizes, int n_in,
                              void* d_out, int out_size) {
    const float* x    = (const float*)d_in[0];
    const float* W    = (const float*)d_in[1];
    const float* bias = (const float*)d_in[2];
    float* out        = (float*)d_out;

    const int gram_smem = (128 * 132 + 256) * 4;                          // 68608 B
    cudaFuncSetAttribute(gram_kernel, cudaFuncAttributeMaxDynamicSharedMemorySize, gram_smem);
    cudaFuncSetAttribute(conv_kernel, cudaFuncAttributeMaxDynamicSharedMemorySize, CONV_SMEM_BYTES);

    transpose_kernel<<<dim3(NT / 32, NB), 256>>>(x);
    prep_w_kernel<<<24, 256>>>(W);
    gram_kernel<<<dim3(NPAIR, NB), 256, gram_smem>>>(x);
    conv_kernel<<<dim3(NT / 64, NB), 256, CONV_SMEM_BYTES>>>(bias, out);
}